// round 13
// baseline (speedup 1.0000x reference)
#include <cuda_runtime.h>

// StealNMSLoss — single fused kernel, vectorized loads, float4-packed factors.
// Interior blocks: double-Sobel composed into separable 5x5 (one smem stage).
// Border blocks: exact nested-clamp two-stage path (scalar).
// Output: scalar f32 = -(1/B) * sum over (C,H,W) of term.
//
// Composed 5x5 (cross-correlation, /64 folded into eps):
//   gxx: col (1,4,6,4,1)   x row (1,0,-2,0,1)
//   gxy: col (-1,-2,0,2,1) x row (-1,-2,0,2,1)
//   gyy: col (1,0,-2,0,1)  x row (1,4,6,4,1)
// Bins on z = gyy*sign(eps-gxy)/(gxx+eps) vs tan(22.5), tan(67.5);
// division-free: compare sign-corrected numerator against t*|den|.

#define HH 512
#define WW 512
#define NIMG 76
#define NBX (WW / 32)
#define NBY (HH / 32)
#define NBLK (NBX * NBY * NIMG)
#define EPSC 1e-7f
#define EPS64 (64.0f * 1e-7f)
#define SE_STRIDE 44

__device__ __align__(16) float g_part[NBLK];
__device__ unsigned int g_cnt;   // zero-init; atomicInc wraps -> deterministic

// Branchless bin classification + loss term. sec points at se center pixel.
// eps is pre-scaled to match gxx/gxy/gyy scaling.
__device__ __forceinline__ float bin_term(float gxx, float gxy, float gyy,
                                          float eps, const float* sec) {
    unsigned sgn = (__float_as_uint(eps - gxy) & 0x80000000u) ^
                   (__float_as_uint(gxx + eps) & 0x80000000u);
    float nn = __uint_as_float(__float_as_uint(gyy) ^ sgn);
    float dd = fabsf(gxx + eps);
    float th1 = 0.41421356237309503f * dd;   // tan(22.5deg)*|den|
    float th2 = 2.41421356237309510f * dd;   // tan(67.5deg)*|den|

    bool vert = (nn >= th2) | (nn < -th2);       // [67.5,112.5)
    bool cd   = !vert && (nn >= th1);            // [22.5,67.5)   taps +-(1,-1)
    bool hz   = !vert && !cd && (nn >= -th1);    // [0,22.5)U[157.5,180) +-(0,1)
    bool ld   = !vert && !cd && !hz && (nn > -th2);  // (112.5,157.5) +-(1,1)

    if (vert | cd | hz | ld) {
        int off = (hz ? 0 : SE_STRIDE) + (vert ? 0 : (cd ? -1 : 1));
        float ec = sec[0];
        float f = sec[-off] + ec + sec[off];
        float r = __fdividef(ec, f + EPSC);
        r = fminf(fmaxf(r, EPSC), 1.0f);
        return __logf(r);
    }
    return 0.0f;
}

__launch_bounds__(256)
__global__ void nms_main_kernel(const float* __restrict__ tl,
                                const float* __restrict__ pl,
                                float* __restrict__ out) {
    // col base for st/se is x0-4 (16B aligned); row base st: y0-2, se: y0-1.
    __shared__ __align__(16) float st[36][40];
    __shared__ __align__(16) float se[34][SE_STRIDE];
    __shared__ union UB {
        float4 h4[36][33];     // interior: {hxx,hxy,hyy,pad} per (row,col)
        float  g[2][34][35];   // border: sgx/sgy first-stage Sobel
    } sb;

    const int x0 = blockIdx.x * 32;
    const int y0 = blockIdx.y * 32;
    const size_t base = (size_t)blockIdx.z * (HH * WW);
    const float* t = tl + base;
    const float* p = pl + base;
    const int tid = threadIdx.y * 32 + threadIdx.x;
    const int tx = threadIdx.x;
    const int ty0 = threadIdx.y * 4;

    const bool border = (blockIdx.x == 0) | (blockIdx.x == NBX - 1) |
                        (blockIdx.y == 0) | (blockIdx.y == NBY - 1);

    float acc = 0.0f;

    if (!border) {
        // ================= interior fast path (vectorized) =================
        const float4* tb4 = (const float4*)(t + (size_t)(y0 - 2) * WW + (x0 - 4));
        for (int j = tid; j < 36 * 10; j += 256) {
            int r = j / 10, c = j - r * 10;
            *(float4*)&st[r][c * 4] = __ldg(tb4 + r * (WW / 4) + c);
        }
        const float4* pb4 = (const float4*)(p + (size_t)(y0 - 1) * WW + (x0 - 4));
        for (int j = tid; j < 34 * 10; j += 256) {
            int r = j / 10, c = j - r * 10;
            float4 v = __ldg(pb4 + r * (WW / 4) + c);
            v.x = __expf(0.1f * v.x); v.y = __expf(0.1f * v.y);
            v.z = __expf(0.1f * v.z); v.w = __expf(0.1f * v.w);
            *(float4*)&se[r][c * 4] = v;
        }
        __syncthreads();

        // horizontal 5-tap factors: 4 output cols per thread from 3 LDS.128
        for (int j = tid; j < 36 * 8; j += 256) {
            int r = j >> 3, g = j & 7, c0 = g * 4;
            float4 a = *(const float4*)&st[r][c0];
            float4 b = *(const float4*)&st[r][c0 + 4];
            float4 c = *(const float4*)&st[r][c0 + 8];
            float s[12] = {a.x, a.y, a.z, a.w, b.x, b.y, b.z, b.w,
                           c.x, c.y, c.z, c.w};
#pragma unroll
            for (int k = 0; k < 4; k++) {
                // output col c0+k uses st cols (c0+k+2 .. c0+k+6)
                float hxx = (s[k + 2] + s[k + 6]) - 2.0f * s[k + 4];
                float hxy = 2.0f * (s[k + 5] - s[k + 3]) + (s[k + 6] - s[k + 2]);
                float hyy = (s[k + 2] + s[k + 6]) + 4.0f * (s[k + 3] + s[k + 5])
                          + 6.0f * s[k + 4];
                sb.h4[r][c0 + k] = make_float4(hxx, hxy, hyy, 0.0f);
            }
        }
        __syncthreads();

        // vertical rolling combine: 4 consecutive rows per thread, LDS.128
        float4 w0 = sb.h4[ty0][tx];
        float4 w1 = sb.h4[ty0 + 1][tx];
        float4 w2 = sb.h4[ty0 + 2][tx];
        float4 w3 = sb.h4[ty0 + 3][tx];
#pragma unroll
        for (int i = 0; i < 4; i++) {
            float4 w4 = sb.h4[ty0 + i + 4][tx];
            const int py = ty0 + i;
            float tc = st[py + 2][tx + 4];
            if (tc > 0.0f) {
                float gxx = (w0.x + w4.x) + 4.0f * (w1.x + w3.x) + 6.0f * w2.x;
                float gxy = (w4.y - w0.y) + 2.0f * (w3.y - w1.y);
                float gyy = (w0.z + w4.z) - 2.0f * w2.z;
                acc += bin_term(gxx, gxy, gyy, EPS64, &se[py + 1][tx + 4]);
            }
            w0 = w1; w1 = w2; w2 = w3; w3 = w4;
        }
    } else {
        // ================= border path (exact nested clamp, scalar) =========
        for (int i = tid; i < 36 * 40; i += 256) {
            int iy = i / 40, ix = i - iy * 40;
            int gy = y0 - 2 + iy; gy = gy < 0 ? 0 : (gy > HH - 1 ? HH - 1 : gy);
            int gx = x0 - 4 + ix; gx = gx < 0 ? 0 : (gx > WW - 1 ? WW - 1 : gx);
            st[iy][ix] = __ldg(t + (size_t)gy * WW + gx);
        }
        for (int i = tid; i < 34 * 40; i += 256) {
            int iy = i / 40, ix = i - iy * 40;
            int gy = y0 - 1 + iy; gy = gy < 0 ? -gy : (gy >= HH ? 2 * HH - 2 - gy : gy);
            int gx = x0 - 4 + ix; gx = gx < 0 ? -gx : (gx >= WW ? 2 * WW - 2 - gx : gx);
            se[iy][ix] = __expf(0.1f * __ldg(p + (size_t)gy * WW + gx));
        }
        __syncthreads();
        // stage 1: first Sobel at CLAMPED global coords (nested replicate pad)
        for (int i = tid; i < 34 * 34; i += 256) {
            int iy = i / 34, ix = i - iy * 34;
            int cy = y0 - 1 + iy; cy = cy < 0 ? 0 : (cy > HH - 1 ? HH - 1 : cy);
            int cx = x0 - 1 + ix; cx = cx < 0 ? 0 : (cx > WW - 1 ? WW - 1 : cx);
            int ay = cy - y0 + 2;
            int ax = cx - x0 + 4;
            float A = st[ay - 1][ax - 1], B = st[ay - 1][ax], C = st[ay - 1][ax + 1];
            float D = st[ay][ax - 1],                          E = st[ay][ax + 1];
            float F = st[ay + 1][ax - 1], G = st[ay + 1][ax], Hv = st[ay + 1][ax + 1];
            sb.g[0][iy][ix] = 0.125f * ((C - A) + 2.0f * (E - D) + (Hv - F));
            sb.g[1][iy][ix] = 0.125f * ((F - A) + 2.0f * (G - B) + (Hv - C));
        }
        __syncthreads();

        // stage 2: rolling 3-row window over sgx/sgy
        float X0, X1, X2, Y0, Y1, Y2, W0, W1, W2;
        {
            float a = sb.g[0][ty0][tx], b = sb.g[0][ty0][tx + 2];
            float c = sb.g[1][ty0][tx], d = sb.g[1][ty0][tx + 1], e = sb.g[1][ty0][tx + 2];
            X0 = b - a; Y0 = e - c; W0 = c + 2.0f * d + e;
            a = sb.g[0][ty0 + 1][tx]; b = sb.g[0][ty0 + 1][tx + 2];
            c = sb.g[1][ty0 + 1][tx]; d = sb.g[1][ty0 + 1][tx + 1]; e = sb.g[1][ty0 + 1][tx + 2];
            X1 = b - a; Y1 = e - c; W1 = c + 2.0f * d + e;
        }
#pragma unroll
        for (int i = 0; i < 4; i++) {
            const int r = ty0 + i + 2;
            {
                float a = sb.g[0][r][tx], b = sb.g[0][r][tx + 2];
                float c = sb.g[1][r][tx], d = sb.g[1][r][tx + 1], e = sb.g[1][r][tx + 2];
                X2 = b - a; Y2 = e - c; W2 = c + 2.0f * d + e;
            }
            const int py = ty0 + i;
            float tc = st[py + 2][tx + 4];
            if (tc > 0.0f) {
                float gxx = 0.125f * (X0 + 2.0f * X1 + X2);
                float gxy = 0.125f * (Y0 + 2.0f * Y1 + Y2);
                float gyy = 0.125f * (W2 - W0);
                acc += bin_term(gxx, gxy, gyy, EPSC, &se[py + 1][tx + 4]);
            }
            X0 = X1; X1 = X2; Y0 = Y1; Y1 = Y2; W0 = W1; W1 = W2;
        }
    }

    // ---- block reduce (float) -> partial slot ----
#pragma unroll
    for (int off = 16; off > 0; off >>= 1)
        acc += __shfl_down_sync(0xffffffffu, acc, off);
    __shared__ float wsum[8];
    if ((tid & 31) == 0) wsum[tid >> 5] = acc;
    __syncthreads();
    const int bid = blockIdx.x + NBX * (blockIdx.y + NBY * blockIdx.z);
    if (tid == 0) {
        g_part[bid] = wsum[0] + wsum[1] + wsum[2] + wsum[3]
                    + wsum[4] + wsum[5] + wsum[6] + wsum[7];
    }

    // ---- last block performs the final reduction (vectorized) ----
    __threadfence();
    __shared__ bool is_last;
    if (tid == 0) {
        unsigned int v = atomicInc(&g_cnt, NBLK - 1);  // wraps -> deterministic
        is_last = (v == NBLK - 1);
    }
    __syncthreads();
    if (is_last) {
        const float4* gp4 = (const float4*)g_part;
        double s = 0.0;
        for (int i = tid; i < NBLK / 4; i += 256) {
            float4 v = __ldcg(&gp4[i]);
            s += (double)v.x + (double)v.y + (double)v.z + (double)v.w;
        }
#pragma unroll
        for (int off = 16; off > 0; off >>= 1)
            s += __shfl_down_sync(0xffffffffu, s, off);
        __shared__ double dsum[8];
        if ((tid & 31) == 0) dsum[tid >> 5] = s;
        __syncthreads();
        if (tid == 0) {
            double tot = dsum[0] + dsum[1] + dsum[2] + dsum[3]
                       + dsum[4] + dsum[5] + dsum[6] + dsum[7];
            out[0] = (float)(-tot * 0.25);   // mean over B=4, negate
        }
    }
}

extern "C" void kernel_launch(void* const* d_in, const int* in_sizes, int n_in,
                              void* d_out, int out_size) {
    const float* tl = (const float*)d_in[0];
    const float* pl = (const float*)d_in[1];
    float* out = (float*)d_out;

    dim3 grid(NBX, NBY, NIMG);
    dim3 block(32, 8);
    nms_main_kernel<<<grid, block>>>(tl, pl, out);
}